// round 16
// baseline (speedup 1.0000x reference)
#include <cuda_runtime.h>
#include <cuda_bf16.h>
#include <cuda_fp16.h>
#include <math.h>
#include <stdint.h>

// Problem constants
#define BATCH   4
#define SEQ     2048
#define DMODEL  1024
#define NHEADS  16
#define DHEAD   64
#define MROWS   (BATCH * SEQ)            // 8192
#define NB_ELEM ((size_t)MROWS * DMODEL)

#define LOSC 1024.0f
#define ILOSC (1.0f / 1024.0f)

// Pipeline buffers
__device__ __half g_qh[MROWS * DMODEL];
__device__ __half g_kh[MROWS * DMODEL];
__device__ __half g_vh[MROWS * DMODEL];
__device__ __half g_oh[MROWS * DMODEL];
__device__ __half g_ol[MROWS * DMODEL];
__device__ __half g_woh[DMODEL * DMODEL];      // wo transposed fp16 hi
__device__ __half g_wol[DMODEL * DMODEL];      // wo transposed fp16 lo
// int8 path (QKV)
__device__ int8_t g_xa1[MROWS * DMODEL];
__device__ int8_t g_xa0[MROWS * DMODEL];
__device__ int8_t g_wb1[3 * DMODEL * DMODEL];  // [n][k], n = 0..3071
__device__ int8_t g_wb0[3 * DMODEL * DMODEL];
__device__ float  g_sx[MROWS];
__device__ float  g_sw[3 * DMODEL];

// ---------------------------------------------------------------------------
// Helpers
// ---------------------------------------------------------------------------
__device__ __forceinline__ uint32_t smem_u32(const void* p) {
    uint32_t a;
    asm("{ .reg .u64 t; cvta.to.shared.u64 t, %1; cvt.u32.u64 %0, t; }" : "=r"(a) : "l"(p));
    return a;
}
__device__ __forceinline__ void split_f16(float x, __half& h, __half& l) {
    h = __float2half_rn(x);
    l = __float2half_rn((x - __half2float(h)) * LOSC);
}
__device__ __forceinline__ uint32_t packh2h(__half a, __half b) {
    __half2 t = __halves2half2(a, b);
    return *reinterpret_cast<uint32_t*>(&t);
}
__device__ __forceinline__ uint32_t packh2(float a, float b) {
    __half2 t = __floats2half2_rn(a, b);
    return *reinterpret_cast<uint32_t*>(&t);
}
__device__ __forceinline__ void mma_f16(float* c, const uint32_t* a, const uint32_t* b) {
    asm("mma.sync.aligned.m16n8k16.row.col.f32.f16.f16.f32 "
        "{%0,%1,%2,%3}, {%4,%5,%6,%7}, {%8,%9}, {%0,%1,%2,%3};"
        : "+f"(c[0]), "+f"(c[1]), "+f"(c[2]), "+f"(c[3])
        : "r"(a[0]), "r"(a[1]), "r"(a[2]), "r"(a[3]), "r"(b[0]), "r"(b[1]));
}
__device__ __forceinline__ void mma_f16h(uint32_t* c, const uint32_t* a, const uint32_t* b) {
    asm("mma.sync.aligned.m16n8k16.row.col.f16.f16.f16.f16 "
        "{%0,%1}, {%2,%3,%4,%5}, {%6,%7}, {%0,%1};"
        : "+r"(c[0]), "+r"(c[1])
        : "r"(a[0]), "r"(a[1]), "r"(a[2]), "r"(a[3]), "r"(b[0]), "r"(b[1]));
}
__device__ __forceinline__ void mma_s8(int* c, const uint32_t* a, const uint32_t* b) {
    asm("mma.sync.aligned.m16n8k32.row.col.s32.s8.s8.s32 "
        "{%0,%1,%2,%3}, {%4,%5,%6,%7}, {%8,%9}, {%0,%1,%2,%3};"
        : "+r"(c[0]), "+r"(c[1]), "+r"(c[2]), "+r"(c[3])
        : "r"(a[0]), "r"(a[1]), "r"(a[2]), "r"(a[3]), "r"(b[0]), "r"(b[1]));
}
__device__ __forceinline__ void ldsm4(uint32_t* r, uint32_t addr) {
    asm volatile("ldmatrix.sync.aligned.m8n8.x4.shared.b16 {%0,%1,%2,%3}, [%4];"
                 : "=r"(r[0]), "=r"(r[1]), "=r"(r[2]), "=r"(r[3]) : "r"(addr));
}
__device__ __forceinline__ void ldsm4t(uint32_t* r, uint32_t addr) {
    asm volatile("ldmatrix.sync.aligned.m8n8.x4.trans.shared.b16 {%0,%1,%2,%3}, [%4];"
                 : "=r"(r[0]), "=r"(r[1]), "=r"(r[2]), "=r"(r[3]) : "r"(addr));
}
__device__ __forceinline__ void cp16(uint32_t dst, const void* src) {
    asm volatile("cp.async.cg.shared.global [%0], [%1], 16;" :: "r"(dst), "l"(src));
}
__device__ __forceinline__ void cp_commit() {
    asm volatile("cp.async.commit_group;");
}

// ---------------------------------------------------------------------------
// Quantize X rows -> int8 hi/lo + per-row scale
// ---------------------------------------------------------------------------
__global__ void quant_rows(const float* __restrict__ X,
                           int8_t* __restrict__ A1, int8_t* __restrict__ A0,
                           float* __restrict__ S) {
    __shared__ float red[8];
    const int row = blockIdx.x;
    const int tid = threadIdx.x;
    const float* xr = X + (size_t)row * DMODEL;

    float m = 0.f;
    #pragma unroll
    for (int i = 0; i < 4; i++) m = fmaxf(m, fabsf(xr[tid + 256 * i]));
    #pragma unroll
    for (int o = 16; o > 0; o >>= 1) m = fmaxf(m, __shfl_xor_sync(0xffffffffu, m, o));
    if ((tid & 31) == 0) red[tid >> 5] = m;
    __syncthreads();
    float mv = red[0];
    #pragma unroll
    for (int j = 1; j < 8; j++) mv = fmaxf(mv, red[j]);
    float s = (mv > 0.f) ? mv / 16256.f : 1.f;
    float inv = 1.f / s;
    if (tid == 0) S[row] = s;

    float4 v = *(const float4*)&xr[tid * 4];
    int q0 = __float2int_rn(v.x * inv);
    int q1 = __float2int_rn(v.y * inv);
    int q2 = __float2int_rn(v.z * inv);
    int q3 = __float2int_rn(v.w * inv);
    int h0 = (q0 + 64) >> 7, h1 = (q1 + 64) >> 7, h2 = (q2 + 64) >> 7, h3 = (q3 + 64) >> 7;
    char4 c1 = make_char4((char)h0, (char)h1, (char)h2, (char)h3);
    char4 c0 = make_char4((char)(q0 - (h0 << 7)), (char)(q1 - (h1 << 7)),
                          (char)(q2 - (h2 << 7)), (char)(q3 - (h3 << 7)));
    *(char4*)&A1[(size_t)row * DMODEL + tid * 4] = c1;
    *(char4*)&A0[(size_t)row * DMODEL + tid * 4] = c0;
}

// ---------------------------------------------------------------------------
// Quantize + transpose QKV weights: W[k][n] -> Bt[n][k] int8 hi/lo, per-col scale.
// grid (32, 1, 3), block (32, 8). blockIdx.z selects weight.
// ---------------------------------------------------------------------------
__global__ void quant_wt(const float* __restrict__ W0, const float* __restrict__ W1,
                         const float* __restrict__ W2,
                         int8_t* __restrict__ B1, int8_t* __restrict__ B0,
                         float* __restrict__ SW) {
    __shared__ float red[8][32];
    __shared__ float sinv[32];
    __shared__ char s1c[32][33];
    __shared__ char s0c[32][33];
    const int w = blockIdx.z;
    const float* W = (w == 0) ? W0 : (w == 1) ? W1 : W2;
    const int n0 = blockIdx.x * 32;
    const int tx = threadIdx.x, ty = threadIdx.y;
    const int t = ty * 32 + tx;

    float m = 0.f;
    for (int k = ty; k < DMODEL; k += 8)
        m = fmaxf(m, fabsf(W[(size_t)k * DMODEL + n0 + tx]));
    red[ty][tx] = m;
    __syncthreads();
    if (ty == 0) {
        #pragma unroll
        for (int j = 1; j < 8; j++) m = fmaxf(m, red[j][tx]);
        float s = (m > 0.f) ? m / 16256.f : 1.f;
        SW[w * DMODEL + n0 + tx] = s;
        sinv[tx] = 1.f / s;
    }
    __syncthreads();

    for (int kc = 0; kc < DMODEL; kc += 32) {
        #pragma unroll
        for (int j = 0; j < 4; j++) {
            int k = ty + 8 * j;
            float v = W[(size_t)(kc + k) * DMODEL + n0 + tx];
            int q = __float2int_rn(v * sinv[tx]);
            int h = (q + 64) >> 7;
            s1c[k][tx] = (char)h;
            s0c[k][tx] = (char)(q - (h << 7));
        }
        __syncthreads();
        {
            int n = t >> 3;
            int c4 = (t & 7) * 4;
            char4 v1 = make_char4(s1c[c4][n], s1c[c4 + 1][n], s1c[c4 + 2][n], s1c[c4 + 3][n]);
            char4 v0 = make_char4(s0c[c4][n], s0c[c4 + 1][n], s0c[c4 + 2][n], s0c[c4 + 3][n]);
            size_t o = (size_t)(w * DMODEL + n0 + n) * DMODEL + kc + c4;
            *(char4*)&B1[o] = v1;
            *(char4*)&B0[o] = v0;
        }
        __syncthreads();
    }
}

// ---------------------------------------------------------------------------
// Split + transpose wo only: W[k][n] -> Ht[n][k], Lt[n][k] fp16
// ---------------------------------------------------------------------------
__global__ void split_wt(const float* __restrict__ W,
                         __half* __restrict__ Ht, __half* __restrict__ Lt) {
    __shared__ float tbuf[32][33];
    const int n0 = blockIdx.x * 32, k0 = blockIdx.y * 32;
    const int tx = threadIdx.x, ty = threadIdx.y;
    #pragma unroll
    for (int i = 0; i < 4; i++)
        tbuf[ty + 8 * i][tx] = W[(size_t)(k0 + ty + 8 * i) * DMODEL + n0 + tx];
    __syncthreads();
    #pragma unroll
    for (int i = 0; i < 4; i++) {
        float v = tbuf[tx][ty + 8 * i];
        __half h, l;
        split_f16(v, h, l);
        size_t o = (size_t)(n0 + ty + 8 * i) * DMODEL + k0 + tx;
        Ht[o] = h;
        Lt[o] = l;
    }
}

// ---------------------------------------------------------------------------
// int8 x3 QKV GEMM with fused RoPE epilogue, fp16 output.
// CTA 128x128, 512 threads (16 warps: 4m x 4n, warp tile 32x32).
// BK=32 (bytes), NSTG=4 stages of 24KB, 3-deep cp.async prefetch.
// ---------------------------------------------------------------------------
#define IRS   48                     // bytes per smem row (32 data + pad)
#define ITSZ  (128 * IRS)            // 6144
#define ISTG  (4 * ITSZ)             // 24576
#define INSTG 4
#define IGSMEM (INSTG * ISTG)        // 98304

__global__ __launch_bounds__(512)
void gemm_i8(const int8_t* __restrict__ A1, const int8_t* __restrict__ A0,
             const int8_t* __restrict__ B1, const int8_t* __restrict__ B0,
             const float* __restrict__ sX, const float* __restrict__ sW,
             __half* __restrict__ QH, __half* __restrict__ KH, __half* __restrict__ VH,
             const int* __restrict__ positions) {
    extern __shared__ char smem[];
    const uint32_t sb = smem_u32(smem);

    const int tid  = threadIdx.x;
    const int lane = tid & 31;
    const int wid  = tid >> 5;          // 0..15
    const int wm   = wid & 3;           // m offset 32*wm
    const int wn   = wid >> 2;          // 0..3
    const int g    = lane >> 2;
    const int tg   = lane & 3;
    const int row0 = blockIdx.y * 128;
    const int col0 = blockIdx.x * 128;

    // cp.async mapping: tile = tid>>7 (A1,A0,B1,B0), row = tid&127, 32B/row
    const int ctile = tid >> 7;
    const int crow  = tid & 127;
    const size_t aoff = (size_t)(row0 + crow) * DMODEL;
    const size_t boff = (size_t)(col0 + crow) * DMODEL;
    const int8_t* mybase = (ctile == 0) ? A1 + aoff
                         : (ctile == 1) ? A0 + aoff
                         : (ctile == 2) ? B1 + boff : B0 + boff;
    const uint32_t mydst0 = (uint32_t)(ctile * ITSZ + crow * IRS);

    // fragment addresses (byte offsets within a tile)
    const int aoffs0 = (wm * 32 + (lane & 15)) * IRS + (lane >> 4) * 16;
    const int nloc   = (wn >> 1) * 64 + (wn & 1) * 16;
    const int brl    = (lane & 7) + ((lane >> 4) << 3);
    const int bby    = ((lane >> 3) & 1) * 16;

    int hi[2][4][4], mid[2][4][4];
    #pragma unroll
    for (int i = 0; i < 2; i++)
        #pragma unroll
        for (int j = 0; j < 4; j++)
            #pragma unroll
            for (int q = 0; q < 4; q++) { hi[i][j][q] = 0; mid[i][j][q] = 0; }

    auto issue = [&](int it) {
        const int st = it & (INSTG - 1);
        const int kc = it * 32;
        uint32_t d = sb + st * ISTG + mydst0;
        cp16(d,      mybase + kc);
        cp16(d + 16, mybase + kc + 16);
        cp_commit();
    };

    const int iters = DMODEL / 32;      // 32
    issue(0); issue(1); issue(2);

    for (int it = 0; it < iters; it++) {
        if (it < iters - 2)
            asm volatile("cp.async.wait_group 2;");
        else if (it < iters - 1)
            asm volatile("cp.async.wait_group 1;");
        else
            asm volatile("cp.async.wait_group 0;");
        __syncthreads();

        if (it + 3 < iters) issue(it + 3);

        const uint32_t base = sb + (it & (INSTG - 1)) * ISTG;
        const uint32_t a1b = base;
        const uint32_t a0b = base + ITSZ;
        const uint32_t b1b = base + 2 * ITSZ;
        const uint32_t b0b = base + 3 * ITSZ;

        uint32_t fa1[2][4], fa0[2][4], fb1[2][4], fb0[2][4];
        #pragma unroll
        for (int mi = 0; mi < 2; mi++) {
            uint32_t off = (uint32_t)(aoffs0 + mi * 16 * IRS);
            ldsm4(fa1[mi], a1b + off);
            ldsm4(fa0[mi], a0b + off);
        }
        #pragma unroll
        for (int p = 0; p < 2; p++) {
            uint32_t off = (uint32_t)((nloc + p * 32 + brl) * IRS + bby);
            ldsm4(fb1[p], b1b + off);
            ldsm4(fb0[p], b0b + off);
        }
        // pass 1: a1*b1 -> hi
        #pragma unroll
        for (int p = 0; p < 2; p++)
            #pragma unroll
            for (int mi = 0; mi < 2; mi++) {
                mma_s8(hi[mi][2 * p],     fa1[mi], fb1[p]);
                mma_s8(hi[mi][2 * p + 1], fa1[mi], fb1[p] + 2);
            }
        // pass 2: a1*b0 -> mid
        #pragma unroll
        for (int p = 0; p < 2; p++)
            #pragma unroll
            for (int mi = 0; mi < 2; mi++) {
                mma_s8(mid[mi][2 * p],     fa1[mi], fb0[p]);
                mma_s8(mid[mi][2 * p + 1], fa1[mi], fb0[p] + 2);
            }
        // pass 3: a0*b1 -> mid
        #pragma unroll
        for (int p = 0; p < 2; p++)
            #pragma unroll
            for (int mi = 0; mi < 2; mi++) {
                mma_s8(mid[mi][2 * p],     fa0[mi], fb1[p]);
                mma_s8(mid[mi][2 * p + 1], fa0[mi], fb1[p] + 2);
            }
    }

    // Epilogue: rescale, RoPE (Q,K), fp16 store.
    const int buf = col0 >> 10;
    __half* dst = (buf == 0) ? QH : (buf == 1) ? KH : VH;
    const int colb = (col0 & (DMODEL - 1)) + nloc;

    float accf[2][4][4];
    #pragma unroll
    for (int mi = 0; mi < 2; mi++) {
        int rg = row0 + wm * 32 + mi * 16 + g;
        float sx0 = sX[rg];
        float sx1 = sX[rg + 8];
        #pragma unroll
        for (int qd = 0; qd < 4; qd++) {
            int gcol = col0 + nloc + (qd >> 1) * 32 + (qd & 1) * 8 + tg * 2;
            float w0 = sW[gcol], w1 = sW[gcol + 1];
            accf[mi][qd][0] = (16384.f * hi[mi][qd][0] + 128.f * mid[mi][qd][0]) * sx0 * w0;
            accf[mi][qd][1] = (16384.f * hi[mi][qd][1] + 128.f * mid[mi][qd][1]) * sx0 * w1;
            accf[mi][qd][2] = (16384.f * hi[mi][qd][2] + 128.f * mid[mi][qd][2]) * sx1 * w0;
            accf[mi][qd][3] = (16384.f * hi[mi][qd][3] + 128.f * mid[mi][qd][3]) * sx1 * w1;
        }
    }

    if (buf < 2) {
        // NeoX rope: quad qd=s (d<32) pairs with qd=2+s (d+32), same warp.
        #pragma unroll
        for (int mi = 0; mi < 2; mi++) {
            int rg = row0 + wm * 32 + mi * 16 + g;
            float p0 = (float)positions[rg & (SEQ - 1)];
            float p1 = (float)positions[(rg + 8) & (SEQ - 1)];
            #pragma unroll
            for (int s = 0; s < 2; s++) {
                #pragma unroll
                for (int q = 0; q < 2; q++) {
                    int d = (wn & 1) * 16 + s * 8 + tg * 2 + q;
                    float invf = exp2f((float)d * -0.4152410118609203f);
                    float c0, s0, c1, s1;
                    sincosf(p0 * invf, &s0, &c0);
                    sincosf(p1 * invf, &s1, &c1);
                    float x1 = accf[mi][s][q],     x2 = accf[mi][2 + s][q];
                    accf[mi][s][q]         = x1 * c0 - x2 * s0;
                    accf[mi][2 + s][q]     = x2 * c0 + x1 * s0;
                    float y1 = accf[mi][s][q + 2], y2 = accf[mi][2 + s][q + 2];
                    accf[mi][s][q + 2]     = y1 * c1 - y2 * s1;
                    accf[mi][2 + s][q + 2] = y2 * c1 + y1 * s1;
                }
            }
        }
    }
    #pragma unroll
    for (int mi = 0; mi < 2; mi++)
        #pragma unroll
        for (int qd = 0; qd < 4; qd++) {
            int rg = row0 + wm * 32 + mi * 16 + g;
            int cg = colb + (qd >> 1) * 32 + (qd & 1) * 8 + tg * 2;
            *(uint32_t*)&dst[(size_t)rg * DMODEL + cg] =
                packh2(accf[mi][qd][0], accf[mi][qd][1]);
            *(uint32_t*)&dst[(size_t)(rg + 8) * DMODEL + cg] =
                packh2(accf[mi][qd][2], accf[mi][qd][3]);
        }
}

// ---------------------------------------------------------------------------
// fp16x2.5-split GEMM (out-projection only). R15 structure: BK=16, NSTG=4,
// 2 CTAs/SM, one sync per iter.
// ---------------------------------------------------------------------------
#define RS   24
#define TSZ  (128 * RS * 2)
#define SSTG (4 * TSZ)
#define NSTG 4
#define GSMEM (NSTG * SSTG)

__global__ __launch_bounds__(256, 2)
void gemm_f16s(const __half* __restrict__ AH, const __half* __restrict__ AL,
               const __half* __restrict__ BHt, const __half* __restrict__ BLt,
               float* __restrict__ C, int M, int N, int K) {
    extern __shared__ char smem[];
    const uint32_t sb = smem_u32(smem);

    const int tid  = threadIdx.x;
    const int lane = tid & 31;
    const int wid  = tid >> 5;
    const int wm   = wid & 3;
    const int wn   = wid >> 2;
    const int g    = lane >> 2;
    const int tg   = lane & 3;
    const int row0 = blockIdx.y * 128;
    const int col0 = blockIdx.x * 128;

    const int am = tid >> 1;
    const int ak = (tid & 1) * 8;

    const int arow  = wm * 32 + (lane & 15);
    const int akoff = (lane >> 4) * 8;
    const int brow  = wn * 64 + (lane & 7) + ((lane >> 4) << 3);
    const int bkoff = ((lane >> 3) & 1) * 8;

    float accf[2][8][4];
    uint32_t acch[2][8][2];
    #pragma unroll
    for (int i = 0; i < 2; i++)
        #pragma unroll
        for (int j = 0; j < 8; j++) {
            #pragma unroll
            for (int q = 0; q < 4; q++) accf[i][j][q] = 0.f;
            acch[i][j][0] = 0u; acch[i][j][1] = 0u;
        }

    auto issue = [&](int it) {
        const int st = it & (NSTG - 1);
        const int kc = it * 16;
        uint32_t ahs = sb + st * SSTG +            (am * RS + ak) * 2;
        uint32_t als = ahs + TSZ;
        uint32_t bhs = sb + st * SSTG + 2 * TSZ + (am * RS + ak) * 2;
        uint32_t bls = bhs + TSZ;
        size_t ab = (size_t)(row0 + am) * K + kc + ak;
        size_t bb = (size_t)(col0 + am) * K + kc + ak;
        cp16(ahs, &AH[ab]);
        cp16(als, &AL[ab]);
        cp16(bhs, &BHt[bb]);
        cp16(bls, &BLt[bb]);
        cp_commit();
    };

    const int iters = K / 16;
    issue(0); issue(1); issue(2);

    for (int it = 0; it < iters; it++) {
        if (it < iters - 2)
            asm volatile("cp.async.wait_group 2;");
        else if (it < iters - 1)
            asm volatile("cp.async.wait_group 1;");
        else
            asm volatile("cp.async.wait_group 0;");
        __syncthreads();

        if (it + 3 < iters) issue(it + 3);

        const uint32_t base = sb + (it & (NSTG - 1)) * SSTG;
        const uint32_t ahb = base;
        const uint32_t alb = base + TSZ;
        const uint32_t bhb = base + 2 * TSZ;
        const uint32_t blb = base + 3 * TSZ;

        uint32_t fah[2][4], fal[2][4], fbh[4][4], fbl[4][4];
        #pragma unroll
        for (int mi = 0; mi < 2; mi++) {
            uint32_t off = (uint32_t)(((arow + mi * 16) * RS + akoff) * 2);
            ldsm4(fah[mi], ahb + off);
            ldsm4(fal[mi], alb + off);
        }
        #pragma unroll
        for (int p = 0; p < 4; p++) {
            uint32_t off = (uint32_t)(((brow + p * 16) * RS + bkoff) * 2);
            ldsm4(fbh[p], bhb + off);
            ldsm4(fbl[p], blb + off);
        }
        #pragma unroll
        for (int p = 0; p < 4; p++)
            #pragma unroll
            for (int mi = 0; mi < 2; mi++) {
                mma_f16(accf[mi][2 * p],     fah[mi], fbh[p]);
                mma_f16(accf[mi][2 * p + 1], fah[mi], fbh[p] + 2);
            }
        #pragma unroll
        for (int p = 0; p < 4; p++)
            #pragma unroll
            for (int mi = 0; mi < 2; mi++) {
                mma_f16h(acch[mi][2 * p],     fah[mi], fbl[p]);
                mma_f16h(acch[mi][2 * p + 1], fah[mi], fbl[p] + 2);
            }
        #pragma unroll
        for (int p = 0; p < 4; p++)
            #pragma unroll
            for (int mi = 0; mi < 2; mi++) {
                mma_f16h(acch[mi][2 * p],     fal[mi], fbh[p]);
                mma_f16h(acch[mi][2 * p + 1], fal[mi], fbh[p] + 2);
            }
    }

    #pragma unroll
    for (int mi = 0; mi < 2; mi++)
        #pragma unroll
        for (int ni = 0; ni < 8; ni++) {
            __half2 h0 = *reinterpret_cast<__half2*>(&acch[mi][ni][0]);
            __half2 h1 = *reinterpret_cast<__half2*>(&acch[mi][ni][1]);
            float c0 = accf[mi][ni][0] + __low2float(h0)  * ILOSC;
            float c1 = accf[mi][ni][1] + __high2float(h0) * ILOSC;
            float c2 = accf[mi][ni][2] + __low2float(h1)  * ILOSC;
            float c3 = accf[mi][ni][3] + __high2float(h1) * ILOSC;
            int rg = row0 + wm * 32 + mi * 16 + g;
            int cg = col0 + wn * 64 + ni * 8 + tg * 2;
            *(float2*)&C[(size_t)rg * N + cg]       = make_float2(c0, c1);
            *(float2*)&C[(size_t)(rg + 8) * N + cg] = make_float2(c2, c3);
        }
}

// ---------------------------------------------------------------------------
// Flash attention v6 (unchanged from R15).
// ---------------------------------------------------------------------------
#define AST 72

__global__ __launch_bounds__(256, 2)
void attn6_kernel(const __half* __restrict__ Q, const __half* __restrict__ K,
                  const __half* __restrict__ V,
                  __half* __restrict__ OH, __half* __restrict__ OL) {
    __shared__ __half sh[128 * AST];
    __half* Qs = sh;
    __half* Kn = sh;
    __half* Vs = sh + 64 * AST;

    const int tid  = threadIdx.x;
    const int lane = tid & 31;
    const int wid  = tid >> 5;
    const int g    = lane >> 2;
    const int tg   = lane & 3;
    const int m0   = wid * 16;

    const int br8 = (lane & 7) + ((lane >> 4) << 3);
    const int bko = ((lane >> 3) & 1) * 8;
    const int vrow = ((lane >> 3) & 1) * 8 + (lane & 7);
    const int vcol = (lane >> 4) * 8;
    const uint32_t knb = smem_u32(Kn);
    const uint32_t vsb = smem_u32(Vs);

    const int bh = blockIdx.y;
    const int b  = bh >> 4;
    const int h  = bh & 15;
    const int q0 = blockIdx.x * 128;
    const size_t base = (size_t)b * SEQ * DMODEL + (size_t)h * DHEAD;

    const int qr = tid >> 3;
    const int d8 = (tid & 7) * 8;

    #pragma unroll
    for (int i = 0; i < 4; i++) {
        int r = qr + 32 * i;
        *(uint4*)&Qs[r * AST + d8] =
            *(const uint4*)&Q[base + (size_t)(q0 + r) * DMODEL + d8];
    }
    __syncthreads();

    uint32_t qa[4][4];
    #pragma unroll
    for (int kst = 0; kst < 4; kst++) {
        int ks = kst * 16 + 2 * tg;
        qa[kst][0] = *(uint32_t*)&Qs[(m0 + g) * AST + ks];
        qa[kst][1] = *(uint32_t*)&Qs[(m0 + g + 8) * AST + ks];
        qa[kst][2] = *(uint32_t*)&Qs[(m0 + g) * AST + ks + 8];
        qa[kst][3] = *(uint32_t*)&Qs[(m0 + g + 8) * AST + ks + 8];
    }

    float accO[8][4];
    #pragma unroll
    for (int i = 0; i < 8; i++)
        #pragma unroll
        for (int j = 0; j < 4; j++) accO[i][j] = 0.f;
    float mr0 = -INFINITY, mr1 = -INFINITY, lr0 = 0.f, lr1 = 0.f;

    for (int kt = 0; kt < SEQ; kt += 64) {
        __syncthreads();
        #pragma unroll
        for (int i = 0; i < 2; i++) {
            int r = qr + 32 * i;
            *(uint4*)&Kn[r * AST + d8] =
                *(const uint4*)&K[base + (size_t)(kt + r) * DMODEL + d8];
            *(uint4*)&Vs[r * AST + d8] =
                *(const uint4*)&V[base + (size_t)(kt + r) * DMODEL + d8];
        }
        __syncthreads();

        float s[8][4];
        #pragma unroll
        for (int i = 0; i < 8; i++)
            #pragma unroll
            for (int j = 0; j < 4; j++) s[i][j] = 0.f;
        #pragma unroll
        for (int kst = 0; kst < 4; kst++) {
            #pragma unroll
            for (int p = 0; p < 4; p++) {
                uint32_t fk[4];
                ldsm4(fk, knb + (uint32_t)(((p * 16 + br8) * AST + kst * 16 + bko) * 2));
                mma_f16(s[2 * p],     qa[kst], fk);
                mma_f16(s[2 * p + 1], qa[kst], fk + 2);
            }
        }

        float nm0 = mr0, nm1 = mr1;
        #pragma unroll
        for (int ni = 0; ni < 8; ni++) {
            nm0 = fmaxf(nm0, fmaxf(s[ni][0], s[ni][1]));
            nm1 = fmaxf(nm1, fmaxf(s[ni][2], s[ni][3]));
        }
        nm0 = fmaxf(nm0, __shfl_xor_sync(0xffffffffu, nm0, 1));
        nm0 = fmaxf(nm0, __shfl_xor_sync(0xffffffffu, nm0, 2));
        nm1 = fmaxf(nm1, __shfl_xor_sync(0xffffffffu, nm1, 1));
        nm1 = fmaxf(nm1, __shfl_xor_sync(0xffffffffu, nm1, 2));
        float a0 = __expf(mr0 - nm0);
        float a1 = __expf(mr1 - nm1);
        float sum0 = 0.f, sum1 = 0.f;
        #pragma unroll
        for (int ni = 0; ni < 8; ni++) {
            s[ni][0] = __expf(s[ni][0] - nm0); sum0 += s[ni][0];
            s[ni][1] = __expf(s[ni][1] - nm0); sum0 += s[ni][1];
            s[ni][2] = __expf(s[ni][2] - nm1); sum1 += s[ni][2];
            s[ni][3] = __expf(s[ni][3] - nm1); sum1 += s[ni][3];
        }
        sum0 += __shfl_xor_sync(0xffffffffu, sum0, 1);
        sum0 += __shfl_xor_sync(0xffffffffu, sum0, 2);
        sum1 += __shfl_xor_sync(0xffffffffu, sum1, 1);
        sum1 += __shfl_xor_sync(0xffffffffu, sum1, 2);
        lr0 = lr0 * a0 + sum0;
        lr1 = lr1 * a1 + sum1;
        mr0 = nm0; mr1 = nm1;

        #pragma unroll
        for (int ni = 0; ni < 8; ni++) {
            accO[ni][0] *= a0; accO[ni][1] *= a0;
            accO[ni][2] *= a1; accO[ni][3] *= a1;
        }

        #pragma unroll
        for (int kst = 0; kst < 4; kst++) {
            uint32_t pf[4];
            pf[0] = packh2(s[2 * kst][0],     s[2 * kst][1]);
            pf[1] = packh2(s[2 * kst][2],     s[2 * kst][3]);
            pf[2] = packh2(s[2 * kst + 1][0], s[2 * kst + 1][1]);
            pf[3] = packh2(s[2 * kst + 1][2], s[2 * kst + 1][3]);
            #pragma unroll
            for (int p = 0; p < 4; p++) {
                uint32_t fv[4];
                ldsm4t(fv, vsb + (uint32_t)(((kst * 16 + vrow) * AST + p * 16 + vcol) * 2));
                mma_f16(accO[2 * p],     pf, fv);
                mma_f16(accO[2 * p + 1], pf, fv + 2);
            }
        }
    }

    {
        float i0 = 1.f / lr0;
        float i1 = 1.f / lr1;
        size_t r0 = base + (size_t)(q0 + m0 + g) * DMODEL;
        size_t r1 = base + (size_t)(q0 + m0 + g + 8) * DMODEL;
        #pragma unroll
        for (int ni = 0; ni < 8; ni++) {
            int c = ni * 8 + 2 * tg;
            float v00 = accO[ni][0] * i0, v01 = accO[ni][1] * i0;
            float v10 = accO[ni][2] * i1, v11 = accO[ni][3] * i1;
            __half h00, l00, h01, l01, h10, l10, h11, l11;
            split_f16(v00, h00, l00); split_f16(v01, h01, l01);
            split_f16(v10, h10, l10); split_f16(v11, h11, l11);
            *(uint32_t*)&OH[r0 + c] = packh2h(h00, h01);
            *(uint32_t*)&OL[r0 + c] = packh2h(l00, l01);
            *(uint32_t*)&OH[r1 + c] = packh2h(h10, h11);
            *(uint32_t*)&OL[r1 + c] = packh2h(l10, l11);
        }
    }
}

// ---------------------------------------------------------------------------
// Launch
// ---------------------------------------------------------------------------
extern "C" void kernel_launch(void* const* d_in, const int* in_sizes, int n_in,
                              void* d_out, int out_size) {
    const int*   positions = (const int*)d_in[0];
    const float* X  = (const float*)d_in[1];
    const float* wq = (const float*)d_in[2];
    const float* wk = (const float*)d_in[3];
    const float* wv = (const float*)d_in[4];
    const float* wo = (const float*)d_in[5];
    float* out = (float*)d_out;

    __half *qh, *kh, *vh, *oh, *ol, *woh, *wol;
    int8_t *xa1, *xa0, *wb1, *wb0;
    float *sx, *sw;
    cudaGetSymbolAddress((void**)&qh, g_qh);
    cudaGetSymbolAddress((void**)&kh, g_kh);
    cudaGetSymbolAddress((void**)&vh, g_vh);
    cudaGetSymbolAddress((void**)&oh, g_oh);
    cudaGetSymbolAddress((void**)&ol, g_ol);
    cudaGetSymbolAddress((void**)&woh, g_woh);
    cudaGetSymbolAddress((void**)&wol, g_wol);
    cudaGetSymbolAddress((void**)&xa1, g_xa1);
    cudaGetSymbolAddress((void**)&xa0, g_xa0);
    cudaGetSymbolAddress((void**)&wb1, g_wb1);
    cudaGetSymbolAddress((void**)&wb0, g_wb0);
    cudaGetSymbolAddress((void**)&sx, g_sx);
    cudaGetSymbolAddress((void**)&sw, g_sw);

    quant_rows<<<MROWS, 256>>>(X, xa1, xa0, sx);
    quant_wt<<<dim3(DMODEL / 32, 1, 3), dim3(32, 8)>>>(wq, wk, wv, wb1, wb0, sw);
    split_wt<<<dim3(DMODEL / 32, DMODEL / 32), dim3(32, 8)>>>(wo, woh, wol);

    cudaFuncSetAttribute(gemm_i8, cudaFuncAttributeMaxDynamicSharedMemorySize, IGSMEM);
    dim3 fgrid(3 * DMODEL / 128, MROWS / 128);   // (24, 64)
    gemm_i8<<<fgrid, 512, IGSMEM>>>(xa1, xa0, wb1, wb0, sx, sw,
                                    qh, kh, vh, positions);

    attn6_kernel<<<dim3(SEQ / 128, BATCH * NHEADS), 256>>>(qh, kh, vh, oh, ol);

    cudaFuncSetAttribute(gemm_f16s, cudaFuncAttributeMaxDynamicSharedMemorySize, GSMEM);
    dim3 ggrid(DMODEL / 128, MROWS / 128);       // (8, 64)
    gemm_f16s<<<ggrid, 256, GSMEM>>>(oh, ol, woh, wol, out, MROWS, DMODEL, DMODEL);
}

// round 17
// speedup vs baseline: 1.0418x; 1.0418x over previous
#include <cuda_runtime.h>
#include <cuda_bf16.h>
#include <cuda_fp16.h>
#include <math.h>
#include <stdint.h>

// Problem constants
#define BATCH   4
#define SEQ     2048
#define DMODEL  1024
#define NHEADS  16
#define DHEAD   64
#define MROWS   (BATCH * SEQ)            // 8192
#define NB_ELEM ((size_t)MROWS * DMODEL)

#define LOSC 1024.0f
#define ILOSC (1.0f / 1024.0f)

// Pipeline buffers
__device__ __half g_qh[MROWS * DMODEL];
__device__ __half g_kh[MROWS * DMODEL];
__device__ __half g_vh[MROWS * DMODEL];
__device__ __half g_oh[MROWS * DMODEL];
__device__ __half g_ol[MROWS * DMODEL];
__device__ __half g_woh[DMODEL * DMODEL];
__device__ __half g_wol[DMODEL * DMODEL];
// int8 path (QKV)
__device__ int8_t g_xa1[MROWS * DMODEL];
__device__ int8_t g_xa0[MROWS * DMODEL];
__device__ int8_t g_wb1[3 * DMODEL * DMODEL];  // [n][k]
__device__ int8_t g_wb0[3 * DMODEL * DMODEL];
__device__ float  g_sx[MROWS];
__device__ float  g_sw[3 * DMODEL];

// ---------------------------------------------------------------------------
// Helpers
// ---------------------------------------------------------------------------
__device__ __forceinline__ uint32_t smem_u32(const void* p) {
    uint32_t a;
    asm("{ .reg .u64 t; cvta.to.shared.u64 t, %1; cvt.u32.u64 %0, t; }" : "=r"(a) : "l"(p));
    return a;
}
__device__ __forceinline__ void split_f16(float x, __half& h, __half& l) {
    h = __float2half_rn(x);
    l = __float2half_rn((x - __half2float(h)) * LOSC);
}
__device__ __forceinline__ uint32_t packh2h(__half a, __half b) {
    __half2 t = __halves2half2(a, b);
    return *reinterpret_cast<uint32_t*>(&t);
}
__device__ __forceinline__ uint32_t packh2(float a, float b) {
    __half2 t = __floats2half2_rn(a, b);
    return *reinterpret_cast<uint32_t*>(&t);
}
__device__ __forceinline__ void mma_f16(float* c, const uint32_t* a, const uint32_t* b) {
    asm("mma.sync.aligned.m16n8k16.row.col.f32.f16.f16.f32 "
        "{%0,%1,%2,%3}, {%4,%5,%6,%7}, {%8,%9}, {%0,%1,%2,%3};"
        : "+f"(c[0]), "+f"(c[1]), "+f"(c[2]), "+f"(c[3])
        : "r"(a[0]), "r"(a[1]), "r"(a[2]), "r"(a[3]), "r"(b[0]), "r"(b[1]));
}
__device__ __forceinline__ void mma_f16h(uint32_t* c, const uint32_t* a, const uint32_t* b) {
    asm("mma.sync.aligned.m16n8k16.row.col.f16.f16.f16.f16 "
        "{%0,%1}, {%2,%3,%4,%5}, {%6,%7}, {%0,%1};"
        : "+r"(c[0]), "+r"(c[1])
        : "r"(a[0]), "r"(a[1]), "r"(a[2]), "r"(a[3]), "r"(b[0]), "r"(b[1]));
}
__device__ __forceinline__ void mma_s8(int* c, const uint32_t* a, const uint32_t* b) {
    asm("mma.sync.aligned.m16n8k32.row.col.s32.s8.s8.s32 "
        "{%0,%1,%2,%3}, {%4,%5,%6,%7}, {%8,%9}, {%0,%1,%2,%3};"
        : "+r"(c[0]), "+r"(c[1]), "+r"(c[2]), "+r"(c[3])
        : "r"(a[0]), "r"(a[1]), "r"(a[2]), "r"(a[3]), "r"(b[0]), "r"(b[1]));
}
__device__ __forceinline__ void ldsm4(uint32_t* r, uint32_t addr) {
    asm volatile("ldmatrix.sync.aligned.m8n8.x4.shared.b16 {%0,%1,%2,%3}, [%4];"
                 : "=r"(r[0]), "=r"(r[1]), "=r"(r[2]), "=r"(r[3]) : "r"(addr));
}
__device__ __forceinline__ void ldsm4t(uint32_t* r, uint32_t addr) {
    asm volatile("ldmatrix.sync.aligned.m8n8.x4.trans.shared.b16 {%0,%1,%2,%3}, [%4];"
                 : "=r"(r[0]), "=r"(r[1]), "=r"(r[2]), "=r"(r[3]) : "r"(addr));
}
__device__ __forceinline__ void cp16(uint32_t dst, const void* src) {
    asm volatile("cp.async.cg.shared.global [%0], [%1], 16;" :: "r"(dst), "l"(src));
}
__device__ __forceinline__ void cp_commit() {
    asm volatile("cp.async.commit_group;");
}

// ---------------------------------------------------------------------------
// Quantize X rows -> int8 hi/lo + per-row scale (R16, proven)
// ---------------------------------------------------------------------------
__global__ void quant_rows(const float* __restrict__ X,
                           int8_t* __restrict__ A1, int8_t* __restrict__ A0,
                           float* __restrict__ S) {
    __shared__ float red[8];
    const int row = blockIdx.x;
    const int tid = threadIdx.x;
    const float* xr = X + (size_t)row * DMODEL;

    float m = 0.f;
    #pragma unroll
    for (int i = 0; i < 4; i++) m = fmaxf(m, fabsf(xr[tid + 256 * i]));
    #pragma unroll
    for (int o = 16; o > 0; o >>= 1) m = fmaxf(m, __shfl_xor_sync(0xffffffffu, m, o));
    if ((tid & 31) == 0) red[tid >> 5] = m;
    __syncthreads();
    float mv = red[0];
    #pragma unroll
    for (int j = 1; j < 8; j++) mv = fmaxf(mv, red[j]);
    float s = (mv > 0.f) ? mv / 16256.f : 1.f;
    float inv = 1.f / s;
    if (tid == 0) S[row] = s;

    float4 v = *(const float4*)&xr[tid * 4];
    int q0 = __float2int_rn(v.x * inv);
    int q1 = __float2int_rn(v.y * inv);
    int q2 = __float2int_rn(v.z * inv);
    int q3 = __float2int_rn(v.w * inv);
    int h0 = (q0 + 64) >> 7, h1 = (q1 + 64) >> 7, h2 = (q2 + 64) >> 7, h3 = (q3 + 64) >> 7;
    char4 c1 = make_char4((char)h0, (char)h1, (char)h2, (char)h3);
    char4 c0 = make_char4((char)(q0 - (h0 << 7)), (char)(q1 - (h1 << 7)),
                          (char)(q2 - (h2 << 7)), (char)(q3 - (h3 << 7)));
    *(char4*)&A1[(size_t)row * DMODEL + tid * 4] = c1;
    *(char4*)&A0[(size_t)row * DMODEL + tid * 4] = c0;
}

// ---------------------------------------------------------------------------
// Quantize + transpose QKV weights (R16, proven)
// ---------------------------------------------------------------------------
__global__ void quant_wt(const float* __restrict__ W0, const float* __restrict__ W1,
                         const float* __restrict__ W2,
                         int8_t* __restrict__ B1, int8_t* __restrict__ B0,
                         float* __restrict__ SW) {
    __shared__ float red[8][32];
    __shared__ float sinv[32];
    __shared__ char s1c[32][33];
    __shared__ char s0c[32][33];
    const int w = blockIdx.z;
    const float* W = (w == 0) ? W0 : (w == 1) ? W1 : W2;
    const int n0 = blockIdx.x * 32;
    const int tx = threadIdx.x, ty = threadIdx.y;
    const int t = ty * 32 + tx;

    float m = 0.f;
    for (int k = ty; k < DMODEL; k += 8)
        m = fmaxf(m, fabsf(W[(size_t)k * DMODEL + n0 + tx]));
    red[ty][tx] = m;
    __syncthreads();
    if (ty == 0) {
        #pragma unroll
        for (int j = 1; j < 8; j++) m = fmaxf(m, red[j][tx]);
        float s = (m > 0.f) ? m / 16256.f : 1.f;
        SW[w * DMODEL + n0 + tx] = s;
        sinv[tx] = 1.f / s;
    }
    __syncthreads();

    for (int kc = 0; kc < DMODEL; kc += 32) {
        #pragma unroll
        for (int j = 0; j < 4; j++) {
            int k = ty + 8 * j;
            float v = W[(size_t)(kc + k) * DMODEL + n0 + tx];
            int q = __float2int_rn(v * sinv[tx]);
            int h = (q + 64) >> 7;
            s1c[k][tx] = (char)h;
            s0c[k][tx] = (char)(q - (h << 7));
        }
        __syncthreads();
        {
            int n = t >> 3;
            int c4 = (t & 7) * 4;
            char4 v1 = make_char4(s1c[c4][n], s1c[c4 + 1][n], s1c[c4 + 2][n], s1c[c4 + 3][n]);
            char4 v0 = make_char4(s0c[c4][n], s0c[c4 + 1][n], s0c[c4 + 2][n], s0c[c4 + 3][n]);
            size_t o = (size_t)(w * DMODEL + n0 + n) * DMODEL + kc + c4;
            *(char4*)&B1[o] = v1;
            *(char4*)&B0[o] = v0;
        }
        __syncthreads();
    }
}

// ---------------------------------------------------------------------------
// Split + transpose wo: W[k][n] -> Ht[n][k], Lt[n][k] fp16
// ---------------------------------------------------------------------------
__global__ void split_wt(const float* __restrict__ W,
                         __half* __restrict__ Ht, __half* __restrict__ Lt) {
    __shared__ float tbuf[32][33];
    const int n0 = blockIdx.x * 32, k0 = blockIdx.y * 32;
    const int tx = threadIdx.x, ty = threadIdx.y;
    #pragma unroll
    for (int i = 0; i < 4; i++)
        tbuf[ty + 8 * i][tx] = W[(size_t)(k0 + ty + 8 * i) * DMODEL + n0 + tx];
    __syncthreads();
    #pragma unroll
    for (int i = 0; i < 4; i++) {
        float v = tbuf[tx][ty + 8 * i];
        __half h, l;
        split_f16(v, h, l);
        size_t o = (size_t)(n0 + ty + 8 * i) * DMODEL + k0 + tx;
        Ht[o] = h;
        Lt[o] = l;
    }
}

// ---------------------------------------------------------------------------
// int8 x3 QKV GEMM v2 — R15 skeleton: 256 threads, 8 warps (m16 x n64),
// CTA tile 128x64, BK=32 bytes, NSTG=4 x 18KB = 72KB -> 2 CTAs/SM,
// 3-deep cp.async prefetch, one sync per iter. Fused RoPE epilogue, fp16 out.
// ---------------------------------------------------------------------------
#define QRS    48                    // smem row stride bytes
#define QA_TSZ (128 * QRS)           // 6144
#define QB_TSZ (64 * QRS)            // 3072
#define QSTG   (2 * QA_TSZ + 2 * QB_TSZ)  // 18432
#define QNSTG  4
#define QGSMEM (QNSTG * QSTG)        // 73728

__global__ __launch_bounds__(256, 2)
void gemm_i8(const int8_t* __restrict__ A1, const int8_t* __restrict__ A0,
             const int8_t* __restrict__ B1, const int8_t* __restrict__ B0,
             const float* __restrict__ sX, const float* __restrict__ sW,
             __half* __restrict__ QH, __half* __restrict__ KH, __half* __restrict__ VH,
             const int* __restrict__ positions) {
    extern __shared__ char smem[];
    const uint32_t sb = smem_u32(smem);

    const int tid  = threadIdx.x;
    const int lane = tid & 31;
    const int wid  = tid >> 5;          // 0..7
    const int g    = lane >> 2;
    const int tg   = lane & 3;
    const int m0   = wid * 16;
    const int row0 = blockIdx.y * 128;
    const int col0 = blockIdx.x * 64;   // global fused column (0..3008)

    // cp.async static mapping
    const int arow_cp = tid & 127;
    const int8_t* aSrc = ((tid >> 7) == 0) ? A1 : A0;
    const uint32_t aDst0 = ((tid >> 7) == 0 ? 0u : (uint32_t)QA_TSZ) + arow_cp * QRS;
    const size_t aGof = (size_t)(row0 + arow_cp) * DMODEL;
    const bool doB = (tid < 128);
    const int brow_cp = tid & 63;
    const int8_t* bSrc = (tid < 64) ? B1 : B0;
    const uint32_t bDst0 = (uint32_t)(2 * QA_TSZ) + ((tid < 64) ? 0u : (uint32_t)QB_TSZ)
                         + brow_cp * QRS;
    const size_t bGof = (size_t)(col0 + brow_cp) * DMODEL;

    // fragment addressing (byte offsets within tiles)
    const int aoffs = (m0 + (lane & 15)) * QRS + (lane >> 4) * 16;
    const int brl   = (lane & 7) + ((lane >> 4) << 3);
    const int bby   = ((lane >> 3) & 1) * 16;

    int hi[8][4], mid[8][4];
    #pragma unroll
    for (int j = 0; j < 8; j++)
        #pragma unroll
        for (int q = 0; q < 4; q++) { hi[j][q] = 0; mid[j][q] = 0; }

    auto issue = [&](int it) {
        const int st = it & (QNSTG - 1);
        const int kc = it * 32;
        uint32_t s0 = sb + st * QSTG;
        const int8_t* ag = aSrc + aGof + kc;
        cp16(s0 + aDst0, ag);
        cp16(s0 + aDst0 + 16, ag + 16);
        if (doB) {
            const int8_t* bg = bSrc + bGof + kc;
            cp16(s0 + bDst0, bg);
            cp16(s0 + bDst0 + 16, bg + 16);
        }
        cp_commit();
    };

    const int iters = DMODEL / 32;      // 32
    issue(0); issue(1); issue(2);

    for (int it = 0; it < iters; it++) {
        if (it < iters - 2)
            asm volatile("cp.async.wait_group 2;");
        else if (it < iters - 1)
            asm volatile("cp.async.wait_group 1;");
        else
            asm volatile("cp.async.wait_group 0;");
        __syncthreads();

        if (it + 3 < iters) issue(it + 3);

        const uint32_t base = sb + (it & (QNSTG - 1)) * QSTG;
        const uint32_t a1b = base;
        const uint32_t a0b = base + QA_TSZ;
        const uint32_t b1b = base + 2 * QA_TSZ;
        const uint32_t b0b = b1b + QB_TSZ;

        uint32_t fa1[4], fa0[4], fb1[4][4], fb0[4][4];
        ldsm4(fa1, a1b + (uint32_t)aoffs);
        ldsm4(fa0, a0b + (uint32_t)aoffs);
        #pragma unroll
        for (int p = 0; p < 4; p++) {
            uint32_t off = (uint32_t)((p * 16 + brl) * QRS + bby);
            ldsm4(fb1[p], b1b + off);
            ldsm4(fb0[p], b0b + off);
        }
        // pass 1: a1*b1 -> hi
        #pragma unroll
        for (int p = 0; p < 4; p++) {
            mma_s8(hi[2 * p],     fa1, fb1[p]);
            mma_s8(hi[2 * p + 1], fa1, fb1[p] + 2);
        }
        // pass 2: a1*b0 -> mid
        #pragma unroll
        for (int p = 0; p < 4; p++) {
            mma_s8(mid[2 * p],     fa1, fb0[p]);
            mma_s8(mid[2 * p + 1], fa1, fb0[p] + 2);
        }
        // pass 3: a0*b1 -> mid
        #pragma unroll
        for (int p = 0; p < 4; p++) {
            mma_s8(mid[2 * p],     fa0, fb1[p]);
            mma_s8(mid[2 * p + 1], fa0, fb1[p] + 2);
        }
    }

    // Epilogue: rescale, RoPE (Q,K), fp16 store.
    const int buf = col0 >> 10;
    __half* dst = (buf == 0) ? QH : (buf == 1) ? KH : VH;
    const int colb = col0 & (DMODEL - 1);

    const int rg0 = row0 + m0 + g;
    const float sx0 = sX[rg0];
    const float sx1 = sX[rg0 + 8];

    float accf[8][4];
    #pragma unroll
    for (int ni = 0; ni < 8; ni++) {
        int gcol = col0 + ni * 8 + tg * 2;
        float w0 = sW[gcol], w1 = sW[gcol + 1];
        accf[ni][0] = (16384.f * hi[ni][0] + 128.f * mid[ni][0]) * sx0 * w0;
        accf[ni][1] = (16384.f * hi[ni][1] + 128.f * mid[ni][1]) * sx0 * w1;
        accf[ni][2] = (16384.f * hi[ni][2] + 128.f * mid[ni][2]) * sx1 * w0;
        accf[ni][3] = (16384.f * hi[ni][3] + 128.f * mid[ni][3]) * sx1 * w1;
    }

    if (buf < 2) {
        // CTA spans exactly one head (64 cols). d = ni*8 + tg*2 + q; pair ni <-> ni+4.
        float p0 = (float)positions[rg0 & (SEQ - 1)];
        float p1 = (float)positions[(rg0 + 8) & (SEQ - 1)];
        #pragma unroll
        for (int ni = 0; ni < 4; ni++) {
            #pragma unroll
            for (int q = 0; q < 2; q++) {
                int d = ni * 8 + tg * 2 + q;
                float invf = exp2f((float)d * -0.4152410118609203f);
                float c0, s0, c1, s1;
                sincosf(p0 * invf, &s0, &c0);
                sincosf(p1 * invf, &s1, &c1);
                float x1 = accf[ni][q],     x2 = accf[ni + 4][q];
                accf[ni][q]         = x1 * c0 - x2 * s0;
                accf[ni + 4][q]     = x2 * c0 + x1 * s0;
                float y1 = accf[ni][q + 2], y2 = accf[ni + 4][q + 2];
                accf[ni][q + 2]     = y1 * c1 - y2 * s1;
                accf[ni + 4][q + 2] = y2 * c1 + y1 * s1;
            }
        }
    }
    #pragma unroll
    for (int ni = 0; ni < 8; ni++) {
        int cg = colb + ni * 8 + tg * 2;
        *(uint32_t*)&dst[(size_t)rg0 * DMODEL + cg] =
            packh2(accf[ni][0], accf[ni][1]);
        *(uint32_t*)&dst[(size_t)(rg0 + 8) * DMODEL + cg] =
            packh2(accf[ni][2], accf[ni][3]);
    }
}

// ---------------------------------------------------------------------------
// fp16x2.5-split GEMM (out-projection). R15 structure (proven).
// ---------------------------------------------------------------------------
#define RS   24
#define TSZ  (128 * RS * 2)
#define SSTG (4 * TSZ)
#define NSTG 4
#define GSMEM (NSTG * SSTG)

__global__ __launch_bounds__(256, 2)
void gemm_f16s(const __half* __restrict__ AH, const __half* __restrict__ AL,
               const __half* __restrict__ BHt, const __half* __restrict__ BLt,
               float* __restrict__ C, int M, int N, int K) {
    extern __shared__ char smem[];
    const uint32_t sb = smem_u32(smem);

    const int tid  = threadIdx.x;
    const int lane = tid & 31;
    const int wid  = tid >> 5;
    const int wm   = wid & 3;
    const int wn   = wid >> 2;
    const int g    = lane >> 2;
    const int tg   = lane & 3;
    const int row0 = blockIdx.y * 128;
    const int col0 = blockIdx.x * 128;

    const int am = tid >> 1;
    const int ak = (tid & 1) * 8;

    const int arow  = wm * 32 + (lane & 15);
    const int akoff = (lane >> 4) * 8;
    const int brow  = wn * 64 + (lane & 7) + ((lane >> 4) << 3);
    const int bkoff = ((lane >> 3) & 1) * 8;

    float accf[2][8][4];
    uint32_t acch[2][8][2];
    #pragma unroll
    for (int i = 0; i < 2; i++)
        #pragma unroll
        for (int j = 0; j < 8; j++) {
            #pragma unroll
            for (int q = 0; q < 4; q++) accf[i][j][q] = 0.f;
            acch[i][j][0] = 0u; acch[i][j][1] = 0u;
        }

    auto issue = [&](int it) {
        const int st = it & (NSTG - 1);
        const int kc = it * 16;
        uint32_t ahs = sb + st * SSTG +            (am * RS + ak) * 2;
        uint32_t als = ahs + TSZ;
        uint32_t bhs = sb + st * SSTG + 2 * TSZ + (am * RS + ak) * 2;
        uint32_t bls = bhs + TSZ;
        size_t ab = (size_t)(row0 + am) * K + kc + ak;
        size_t bb = (size_t)(col0 + am) * K + kc + ak;
        cp16(ahs, &AH[ab]);
        cp16(als, &AL[ab]);
        cp16(bhs, &BHt[bb]);
        cp16(bls, &BLt[bb]);
        cp_commit();
    };

    const int iters = K / 16;
    issue(0); issue(1); issue(2);

    for (int it = 0; it < iters; it++) {
        if (it < iters - 2)
            asm volatile("cp.async.wait_group 2;");
        else if (it < iters - 1)
            asm volatile("cp.async.wait_group 1;");
        else
            asm volatile("cp.async.wait_group 0;");
        __syncthreads();

        if (it + 3 < iters) issue(it + 3);

        const uint32_t base = sb + (it & (NSTG - 1)) * SSTG;
        const uint32_t ahb = base;
        const uint32_t alb = base + TSZ;
        const uint32_t bhb = base + 2 * TSZ;
        const uint32_t blb = base + 3 * TSZ;

        uint32_t fah[2][4], fal[2][4], fbh[4][4], fbl[4][4];
        #pragma unroll
        for (int mi = 0; mi < 2; mi++) {
            uint32_t off = (uint32_t)(((arow + mi * 16) * RS + akoff) * 2);
            ldsm4(fah[mi], ahb + off);
            ldsm4(fal[mi], alb + off);
        }
        #pragma unroll
        for (int p = 0; p < 4; p++) {
            uint32_t off = (uint32_t)(((brow + p * 16) * RS + bkoff) * 2);
            ldsm4(fbh[p], bhb + off);
            ldsm4(fbl[p], blb + off);
        }
        #pragma unroll
        for (int p = 0; p < 4; p++)
            #pragma unroll
            for (int mi = 0; mi < 2; mi++) {
                mma_f16(accf[mi][2 * p],     fah[mi], fbh[p]);
                mma_f16(accf[mi][2 * p + 1], fah[mi], fbh[p] + 2);
            }
        #pragma unroll
        for (int p = 0; p < 4; p++)
            #pragma unroll
            for (int mi = 0; mi < 2; mi++) {
                mma_f16h(acch[mi][2 * p],     fah[mi], fbl[p]);
                mma_f16h(acch[mi][2 * p + 1], fah[mi], fbl[p] + 2);
            }
        #pragma unroll
        for (int p = 0; p < 4; p++)
            #pragma unroll
            for (int mi = 0; mi < 2; mi++) {
                mma_f16h(acch[mi][2 * p],     fal[mi], fbh[p]);
                mma_f16h(acch[mi][2 * p + 1], fal[mi], fbh[p] + 2);
            }
    }

    #pragma unroll
    for (int mi = 0; mi < 2; mi++)
        #pragma unroll
        for (int ni = 0; ni < 8; ni++) {
            __half2 h0 = *reinterpret_cast<__half2*>(&acch[mi][ni][0]);
            __half2 h1 = *reinterpret_cast<__half2*>(&acch[mi][ni][1]);
            float c0 = accf[mi][ni][0] + __low2float(h0)  * ILOSC;
            float c1 = accf[mi][ni][1] + __high2float(h0) * ILOSC;
            float c2 = accf[mi][ni][2] + __low2float(h1)  * ILOSC;
            float c3 = accf[mi][ni][3] + __high2float(h1) * ILOSC;
            int rg = row0 + wm * 32 + mi * 16 + g;
            int cg = col0 + wn * 64 + ni * 8 + tg * 2;
            *(float2*)&C[(size_t)rg * N + cg]       = make_float2(c0, c1);
            *(float2*)&C[(size_t)(rg + 8) * N + cg] = make_float2(c2, c3);
        }
}

// ---------------------------------------------------------------------------
// Flash attention v6 (unchanged from R15).
// ---------------------------------------------------------------------------
#define AST 72

__global__ __launch_bounds__(256, 2)
void attn6_kernel(const __half* __restrict__ Q, const __half* __restrict__ K,
                  const __half* __restrict__ V,
                  __half* __restrict__ OH, __half* __restrict__ OL) {
    __shared__ __half sh[128 * AST];
    __half* Qs = sh;
    __half* Kn = sh;
    __half* Vs = sh + 64 * AST;

    const int tid  = threadIdx.x;
    const int lane = tid & 31;
    const int wid  = tid >> 5;
    const int g    = lane >> 2;
    const int tg   = lane & 3;
    const int m0   = wid * 16;

    const int br8 = (lane & 7) + ((lane >> 4) << 3);
    const int bko = ((lane >> 3) & 1) * 8;
    const int vrow = ((lane >> 3) & 1) * 8 + (lane & 7);
    const int vcol = (lane >> 4) * 8;
    const uint32_t knb = smem_u32(Kn);
    const uint32_t vsb = smem_u32(Vs);

    const int bh = blockIdx.y;
    const int b  = bh >> 4;
    const int h  = bh & 15;
    const int q0 = blockIdx.x * 128;
    const size_t base = (size_t)b * SEQ * DMODEL + (size_t)h * DHEAD;

    const int qr = tid >> 3;
    const int d8 = (tid & 7) * 8;

    #pragma unroll
    for (int i = 0; i < 4; i++) {
        int r = qr + 32 * i;
        *(uint4*)&Qs[r * AST + d8] =
            *(const uint4*)&Q[base + (size_t)(q0 + r) * DMODEL + d8];
    }
    __syncthreads();

    uint32_t qa[4][4];
    #pragma unroll
    for (int kst = 0; kst < 4; kst++) {
        int ks = kst * 16 + 2 * tg;
        qa[kst][0] = *(uint32_t*)&Qs[(m0 + g) * AST + ks];
        qa[kst][1] = *(uint32_t*)&Qs[(m0 + g + 8) * AST + ks];
        qa[kst][2] = *(uint32_t*)&Qs[(m0 + g) * AST + ks + 8];
        qa[kst][3] = *(uint32_t*)&Qs[(m0 + g + 8) * AST + ks + 8];
    }

    float accO[8][4];
    #pragma unroll
    for (int i = 0; i < 8; i++)
        #pragma unroll
        for (int j = 0; j < 4; j++) accO[i][j] = 0.f;
    float mr0 = -INFINITY, mr1 = -INFINITY, lr0 = 0.f, lr1 = 0.f;

    for (int kt = 0; kt < SEQ; kt += 64) {
        __syncthreads();
        #pragma unroll
        for (int i = 0; i < 2; i++) {
            int r = qr + 32 * i;
            *(uint4*)&Kn[r * AST + d8] =
                *(const uint4*)&K[base + (size_t)(kt + r) * DMODEL + d8];
            *(uint4*)&Vs[r * AST + d8] =
                *(const uint4*)&V[base + (size_t)(kt + r) * DMODEL + d8];
        }
        __syncthreads();

        float s[8][4];
        #pragma unroll
        for (int i = 0; i < 8; i++)
            #pragma unroll
            for (int j = 0; j < 4; j++) s[i][j] = 0.f;
        #pragma unroll
        for (int kst = 0; kst < 4; kst++) {
            #pragma unroll
            for (int p = 0; p < 4; p++) {
                uint32_t fk[4];
                ldsm4(fk, knb + (uint32_t)(((p * 16 + br8) * AST + kst * 16 + bko) * 2));
                mma_f16(s[2 * p],     qa[kst], fk);
                mma_f16(s[2 * p + 1], qa[kst], fk + 2);
            }
        }

        float nm0 = mr0, nm1 = mr1;
        #pragma unroll
        for (int ni = 0; ni < 8; ni++) {
            nm0 = fmaxf(nm0, fmaxf(s[ni][0], s[ni][1]));
            nm1 = fmaxf(nm1, fmaxf(s[ni][2], s[ni][3]));
        }
        nm0 = fmaxf(nm0, __shfl_xor_sync(0xffffffffu, nm0, 1));
        nm0 = fmaxf(nm0, __shfl_xor_sync(0xffffffffu, nm0, 2));
        nm1 = fmaxf(nm1, __shfl_xor_sync(0xffffffffu, nm1, 1));
        nm1 = fmaxf(nm1, __shfl_xor_sync(0xffffffffu, nm1, 2));
        float a0 = __expf(mr0 - nm0);
        float a1 = __expf(mr1 - nm1);
        float sum0 = 0.f, sum1 = 0.f;
        #pragma unroll
        for (int ni = 0; ni < 8; ni++) {
            s[ni][0] = __expf(s[ni][0] - nm0); sum0 += s[ni][0];
            s[ni][1] = __expf(s[ni][1] - nm0); sum0 += s[ni][1];
            s[ni][2] = __expf(s[ni][2] - nm1); sum1 += s[ni][2];
            s[ni][3] = __expf(s[ni][3] - nm1); sum1 += s[ni][3];
        }
        sum0 += __shfl_xor_sync(0xffffffffu, sum0, 1);
        sum0 += __shfl_xor_sync(0xffffffffu, sum0, 2);
        sum1 += __shfl_xor_sync(0xffffffffu, sum1, 1);
        sum1 += __shfl_xor_sync(0xffffffffu, sum1, 2);
        lr0 = lr0 * a0 + sum0;
        lr1 = lr1 * a1 + sum1;
        mr0 = nm0; mr1 = nm1;

        #pragma unroll
        for (int ni = 0; ni < 8; ni++) {
            accO[ni][0] *= a0; accO[ni][1] *= a0;
            accO[ni][2] *= a1; accO[ni][3] *= a1;
        }

        #pragma unroll
        for (int kst = 0; kst < 4; kst++) {
            uint32_t pf[4];
            pf[0] = packh2(s[2 * kst][0],     s[2 * kst][1]);
            pf[1] = packh2(s[2 * kst][2],     s[2 * kst][3]);
            pf[2] = packh2(s[2 * kst + 1][0], s[2 * kst + 1][1]);
            pf[3] = packh2(s[2 * kst + 1][2], s[2 * kst + 1][3]);
            #pragma unroll
            for (int p = 0; p < 4; p++) {
                uint32_t fv[4];
                ldsm4t(fv, vsb + (uint32_t)(((kst * 16 + vrow) * AST + p * 16 + vcol) * 2));
                mma_f16(accO[2 * p],     pf, fv);
                mma_f16(accO[2 * p + 1], pf, fv + 2);
            }
        }
    }

    {
        float i0 = 1.f / lr0;
        float i1 = 1.f / lr1;
        size_t r0 = base + (size_t)(q0 + m0 + g) * DMODEL;
        size_t r1 = base + (size_t)(q0 + m0 + g + 8) * DMODEL;
        #pragma unroll
        for (int ni = 0; ni < 8; ni++) {
            int c = ni * 8 + 2 * tg;
            float v00 = accO[ni][0] * i0, v01 = accO[ni][1] * i0;
            float v10 = accO[ni][2] * i1, v11 = accO[ni][3] * i1;
            __half h00, l00, h01, l01, h10, l10, h11, l11;
            split_f16(v00, h00, l00); split_f16(v01, h01, l01);
            split_f16(v10, h10, l10); split_f16(v11, h11, l11);
            *(uint32_t*)&OH[r0 + c] = packh2h(h00, h01);
            *(uint32_t*)&OL[r0 + c] = packh2h(l00, l01);
            *(uint32_t*)&OH[r1 + c] = packh2h(h10, h11);
            *(uint32_t*)&OL[r1 + c] = packh2h(l10, l11);
        }
    }
}

// ---------------------------------------------------------------------------
// Launch
// ---------------------------------------------------------------------------
extern "C" void kernel_launch(void* const* d_in, const int* in_sizes, int n_in,
                              void* d_out, int out_size) {
    const int*   positions = (const int*)d_in[0];
    const float* X  = (const float*)d_in[1];
    const float* wq = (const float*)d_in[2];
    const float* wk = (const float*)d_in[3];
    const float* wv = (const float*)d_in[4];
    const float* wo = (const float*)d_in[5];
    float* out = (float*)d_out;

    __half *qh, *kh, *vh, *oh, *ol, *woh, *wol;
    int8_t *xa1, *xa0, *wb1, *wb0;
    float *sx, *sw;
    cudaGetSymbolAddress((void**)&qh, g_qh);
    cudaGetSymbolAddress((void**)&kh, g_kh);
    cudaGetSymbolAddress((void**)&vh, g_vh);
    cudaGetSymbolAddress((void**)&oh, g_oh);
    cudaGetSymbolAddress((void**)&ol, g_ol);
    cudaGetSymbolAddress((void**)&woh, g_woh);
    cudaGetSymbolAddress((void**)&wol, g_wol);
    cudaGetSymbolAddress((void**)&xa1, g_xa1);
    cudaGetSymbolAddress((void**)&xa0, g_xa0);
    cudaGetSymbolAddress((void**)&wb1, g_wb1);
    cudaGetSymbolAddress((void**)&wb0, g_wb0);
    cudaGetSymbolAddress((void**)&sx, g_sx);
    cudaGetSymbolAddress((void**)&sw, g_sw);

    quant_rows<<<MROWS, 256>>>(X, xa1, xa0, sx);
    quant_wt<<<dim3(DMODEL / 32, 1, 3), dim3(32, 8)>>>(wq, wk, wv, wb1, wb0, sw);
    split_wt<<<dim3(DMODEL / 32, DMODEL / 32), dim3(32, 8)>>>(wo, woh, wol);

    cudaFuncSetAttribute(gemm_i8, cudaFuncAttributeMaxDynamicSharedMemorySize, QGSMEM);
    dim3 qgrid(3 * DMODEL / 64, MROWS / 128);    // (48, 64)
    gemm_i8<<<qgrid, 256, QGSMEM>>>(xa1, xa0, wb1, wb0, sx, sw,
                                    qh, kh, vh, positions);

    attn6_kernel<<<dim3(SEQ / 128, BATCH * NHEADS), 256>>>(qh, kh, vh, oh, ol);

    cudaFuncSetAttribute(gemm_f16s, cudaFuncAttributeMaxDynamicSharedMemorySize, GSMEM);
    dim3 ggrid(DMODEL / 128, MROWS / 128);       // (8, 64)
    gemm_f16s<<<ggrid, 256, GSMEM>>>(oh, ol, woh, wol, out, MROWS, DMODEL, DMODEL);
}